// round 4
// baseline (speedup 1.0000x reference)
#include <cuda_runtime.h>
#include <cstdint>

// Problem constants (fixed shape instance)
constexpr int B = 64;
constexpr int Q = 1024;
constexpr int N = 2048;
constexpr int C = 2048;
constexpr int P = 512;
constexpr int W = 256;
constexpr int HALF = W / 2;

// GEMM tiling: block tile 64b x 64j x 32k; grid = 8 j-tiles x 64 k-splits = 512
constexpr int KC   = 32;
constexpr int KS   = C / KC;   // 64
constexpr int JT   = 64;
constexpr int NJT  = P / JT;   // 8
constexpr int SST  = 68;       // smem row stride (floats): 16B-chunk stride 17 -> conflict-free
constexpr int GRID = NJT * KS; // 512 blocks, all co-resident (<= 4/SM * 148)
constexpr int NTHR = 256;

// Scratch (__device__ globals: allocation-free rule)
__device__ float d_Hpart[KS * B * P];       // 8 MB split partials (L2-resident)
__device__ float d_gw[B * W];
__device__ int   d_base[B];
__device__ unsigned int d_bar_count = 0;    // grid barrier state
__device__ unsigned int d_bar_sense = 0;

__device__ __forceinline__ unsigned long long pk2(float lo, float hi) {
    unsigned long long r;
    asm("mov.b64 %0, {%1, %2};" : "=l"(r) : "f"(lo), "f"(hi));
    return r;
}
__device__ __forceinline__ void fma2(unsigned long long& d,
                                     unsigned long long a, unsigned long long b) {
    asm("fma.rn.f32x2 %0, %1, %2, %0;" : "+l"(d) : "l"(a), "l"(b));
}

// Sense-reversal grid barrier. Safe: all GRID blocks are co-resident
// (launch_bounds caps regs at 64 -> 4 blocks/SM; smem 17.5KB -> 4/SM fits).
// Resets count each use; sense is a monotonically increasing generation, so
// graph replays are handled by reading the base generation at kernel entry.
__device__ __forceinline__ void grid_barrier(unsigned int target) {
    __syncthreads();
    if (threadIdx.x == 0) {
        __threadfence();                         // publish this block's writes
        unsigned int arrived = atomicAdd(&d_bar_count, 1u);
        if (arrived == GRID - 1) {
            d_bar_count = 0;                     // sole writer at this point
            __threadfence();
            atomicAdd(&d_bar_sense, 1u);         // release
        } else {
            while ((int)(*(volatile unsigned int*)&d_bar_sense - target) < 0)
                __nanosleep(64);
        }
        __threadfence();                         // acquire
    }
    __syncthreads();
}

// ---------------------------------------------------------------------------
// Fused persistent kernel: GEMM -> barrier -> head -> barrier -> window-sum
// ---------------------------------------------------------------------------
__global__ __launch_bounds__(NTHR, 4) void fused_kernel(
    const float* __restrict__ q_i,   // (B,Q,N)
    const float* __restrict__ c_t,   // (B,C)
    const float* __restrict__ w_p,   // (P,C)
    const float* __restrict__ v_p,   // (1,P)
    float* __restrict__ out)         // (B,Q)
{
    __shared__ float pool[2 * KC * SST];   // 17408 B, reused across phases
    __shared__ float wpart[4];
    __shared__ float s_pt;
    __shared__ int   s_p;
    __shared__ int   s_base;

    const int bid = blockIdx.x;
    const int t   = threadIdx.x;

    // Barrier generation base for this launch (same value seen by all blocks:
    // sense cannot advance until every block has passed this point).
    const unsigned int gen0 = *(volatile unsigned int*)&d_bar_sense;

    // ======================= Phase 1: split-K GEMM =========================
    // Hpart[ks][b][j] = sum_{k in chunk ks} c_t[b,k] * w_p[j,k]
    {
        float (*sc)[SST] = reinterpret_cast<float(*)[SST]>(pool);            // 32k x 64b
        float (*sw)[SST] = reinterpret_cast<float(*)[SST]>(pool + KC * SST); // 32k x 64j

        const int jt = bid & (NJT - 1);
        const int ks = bid >> 3;
        const int k0 = ks * KC;
        const int kl  = t & 31;
        const int grp = t >> 5;      // 0..7

        // c tile: 16 b-quads, 2 per group (transposed store, conflict-free)
#pragma unroll
        for (int it = 0; it < 2; it++) {
            int bq = grp + 8 * it;
            const float* cr = c_t + (size_t)(bq * 4) * C + k0 + kl;
            float v0 = __ldg(cr);
            float v1 = __ldg(cr + C);
            float v2 = __ldg(cr + 2 * C);
            float v3 = __ldg(cr + 3 * C);
            *reinterpret_cast<float4*>(&sc[kl][bq * 4]) = make_float4(v0, v1, v2, v3);
        }
        // w tile: 16 j-quads
#pragma unroll
        for (int it = 0; it < 2; it++) {
            int jq = grp + 8 * it;
            const float* wr = w_p + (size_t)(jt * JT + jq * 4) * C + k0 + kl;
            float v0 = __ldg(wr);
            float v1 = __ldg(wr + C);
            float v2 = __ldg(wr + 2 * C);
            float v3 = __ldg(wr + 3 * C);
            *reinterpret_cast<float4*>(&sw[kl][jq * 4]) = make_float4(v0, v1, v2, v3);
        }
        __syncthreads();

        const int jg = t & 15;
        const int bg = t >> 4;
        const int b0 = bg * 4;
        const int j0 = jg * 4;

        unsigned long long acc[4][2];   // [bb][j-pair]
#pragma unroll
        for (int bb = 0; bb < 4; bb++) { acc[bb][0] = 0ull; acc[bb][1] = 0ull; }

#pragma unroll 8
        for (int k = 0; k < KC; k++) {
            float4 ca = *reinterpret_cast<const float4*>(&sc[k][b0]);
            ulonglong2 wv = *reinterpret_cast<const ulonglong2*>(&sw[k][j0]);
            unsigned long long cd0 = pk2(ca.x, ca.x);
            unsigned long long cd1 = pk2(ca.y, ca.y);
            unsigned long long cd2 = pk2(ca.z, ca.z);
            unsigned long long cd3 = pk2(ca.w, ca.w);
            fma2(acc[0][0], cd0, wv.x); fma2(acc[0][1], cd0, wv.y);
            fma2(acc[1][0], cd1, wv.x); fma2(acc[1][1], cd1, wv.y);
            fma2(acc[2][0], cd2, wv.x); fma2(acc[2][1], cd2, wv.y);
            fma2(acc[3][0], cd3, wv.x); fma2(acc[3][1], cd3, wv.y);
        }

#pragma unroll
        for (int bb = 0; bb < 4; bb++) {
            size_t row = ((size_t)ks * B + (b0 + bb)) * P + jt * JT + j0;
            *reinterpret_cast<ulonglong2*>(&d_Hpart[row]) =
                make_ulonglong2(acc[bb][0], acc[bb][1]);
        }
    }

    grid_barrier(gen0 + 1);

    // ======================= Phase 2: head (64 blocks) ======================
    if (bid < B) {
        const int b  = bid;
        const int g2 = t >> 7;       // 0..1 split group
        const int jq = t & 127;      // j quad

        float4 s = make_float4(0.f, 0.f, 0.f, 0.f);
#pragma unroll
        for (int sft = 0; sft < KS / 2; sft++) {
            int ks = g2 + 2 * sft;
            float4 h = *reinterpret_cast<const float4*>(
                &d_Hpart[((size_t)ks * B + b) * P + jq * 4]);
            s.x += h.x; s.y += h.y; s.z += h.z; s.w += h.w;
        }
        float4* hs = reinterpret_cast<float4*>(pool);   // 2 x 128 float4
        hs[g2 * 128 + jq] = s;
        __syncthreads();

        if (t < 128) {
            float4 a  = hs[t];
            float4 b4 = hs[128 + t];
            float part = v_p[t * 4 + 0] * tanhf(a.x + b4.x)
                       + v_p[t * 4 + 1] * tanhf(a.y + b4.y)
                       + v_p[t * 4 + 2] * tanhf(a.z + b4.z)
                       + v_p[t * 4 + 3] * tanhf(a.w + b4.w);
#pragma unroll
            for (int o = 16; o > 0; o >>= 1)
                part += __shfl_down_sync(0xffffffffu, part, o);
            if ((t & 31) == 0) wpart[t >> 5] = part;
        }
        __syncthreads();

        if (t == 0) {
            float x   = ((wpart[0] + wpart[1]) + wpart[2]) + wpart[3];
            float loc = 1.f / (1.f + expf(-x));
            float pt  = loc * (float)(N - 1);     // loc * 2047
            int   p   = (int)rintf(pt);           // round-half-even == jnp.round
            s_pt = pt;
            s_p  = p;
            int base = p - HALF;
            if (base < 0) base = 0;
            if (base > N - W) base = N - W;
            d_base[b] = base;
        }
        __syncthreads();

        if (t < W) {
            int n = s_p - HALF + t;
            float d = ((float)n - s_pt) * (1.0f / (float)HALF);
            d_gw[b * W + t] = expf(-2.f * d * d);
        }
    }

    grid_barrier(gen0 + 2);

    // ======================= Phase 3: window sum ============================
    // s_t[b,q] = sum_w g[b,w] * q_i[b, q, base + w]; 128 rows per block.
    {
        const int b  = bid >> 3;            // single batch per block
        const int q0 = (bid & 7) * 128;

        float* g = pool;
        if (t < W) g[t] = d_gw[b * W + t];
        if (t == 0) s_base = d_base[b];
        __syncthreads();

        const int warp = t >> 5, lane = t & 31;

        float gw[8];
#pragma unroll
        for (int i = 0; i < 8; i++) gw[i] = g[lane + 32 * i];

        const float* rowbase = q_i + ((size_t)b * Q + q0 + warp * 16) * N + s_base;
        float* outbase = out + (size_t)b * Q + q0 + warp * 16;

#pragma unroll 2
        for (int r = 0; r < 16; r += 2) {
            const float* r0 = rowbase + (size_t)r * N;
            const float* r1 = r0 + N;
            float x0[8], x1[8];
#pragma unroll
            for (int i = 0; i < 8; i++) x0[i] = __ldg(r0 + lane + 32 * i);
#pragma unroll
            for (int i = 0; i < 8; i++) x1[i] = __ldg(r1 + lane + 32 * i);
            float a0 = 0.f, a1 = 0.f;
#pragma unroll
            for (int i = 0; i < 8; i++) { a0 += gw[i] * x0[i]; a1 += gw[i] * x1[i]; }
#pragma unroll
            for (int o = 16; o > 0; o >>= 1) {
                a0 += __shfl_down_sync(0xffffffffu, a0, o);
                a1 += __shfl_down_sync(0xffffffffu, a1, o);
            }
            if (lane == 0) { outbase[r] = a0; outbase[r + 1] = a1; }
        }
    }
}

// ---------------------------------------------------------------------------
extern "C" void kernel_launch(void* const* d_in, const int* in_sizes, int n_in,
                              void* d_out, int out_size)
{
    const float* q_i = (const float*)d_in[0];  // (B,Q,N)
    const float* c_t = (const float*)d_in[1];  // (B,C)
    // d_in[2] = w_a : cancels (softmax over singleton axis == 1)
    const float* w_p = (const float*)d_in[3];  // (P,C)
    const float* v_p = (const float*)d_in[4];  // (1,P)
    float* out = (float*)d_out;                // (B,Q)

    fused_kernel<<<GRID, NTHR>>>(q_i, c_t, w_p, v_p, out);
}